// round 1
// baseline (speedup 1.0000x reference)
#include <cuda_runtime.h>

// GraphAppnp: fused sum-aggregation + APPNP alpha blend.
// Inputs (metadata order): x[N,D], neighbor_agg[N,K,D], h[N,D], neighbor[N,K,D]
// Outputs (concatenated): x_out[N,D] then nbr_out[N,K,D]
// N=50000, K=32, D=64, ALPHA=0.1

#define ALPHA     0.1f
#define ONE_M_A   0.9f
#define KNBR      32
#define DDIM      64
#define D4        16          // D / 4 float4 per row
#define THREADS_PER_NODE 16   // one float4 per thread across D

__global__ __launch_bounds__(256)
void appnp_fused_kernel(const float4* __restrict__ x,
                        const float4* __restrict__ nagg,
                        const float4* __restrict__ h,
                        const float4* __restrict__ nbr,
                        float4* __restrict__ out_x,
                        float4* __restrict__ out_nbr,
                        int n_nodes)
{
    int gtid = blockIdx.x * blockDim.x + threadIdx.x;
    int node = gtid >> 4;          // / THREADS_PER_NODE
    int d4   = gtid & 15;          // % THREADS_PER_NODE
    if (node >= n_nodes) return;

    size_t row_base = (size_t)node * (KNBR * D4) + d4;
    const float4* na_p  = nagg   + row_base;
    const float4* nb_p  = nbr    + row_base;
    float4*       out_p = out_nbr + row_base;

    size_t xr = (size_t)node * D4 + d4;
    float4 xv = x[xr];

    float4 acc = make_float4(0.f, 0.f, 0.f, 0.f);

    #pragma unroll 8
    for (int k = 0; k < KNBR; ++k) {
        float4 a = na_p[(size_t)k * D4];
        float4 b = nb_p[(size_t)k * D4];

        acc.x += a.x; acc.y += a.y; acc.z += a.z; acc.w += a.w;

        float4 o;
        o.x = fmaf(ONE_M_A, a.x + xv.x, ALPHA * b.x);
        o.y = fmaf(ONE_M_A, a.y + xv.y, ALPHA * b.y);
        o.z = fmaf(ONE_M_A, a.z + xv.z, ALPHA * b.z);
        o.w = fmaf(ONE_M_A, a.w + xv.w, ALPHA * b.w);
        out_p[(size_t)k * D4] = o;
    }

    float4 hv = h[xr];
    float4 xo;
    xo.x = fmaf(ONE_M_A, xv.x + acc.x, ALPHA * hv.x);
    xo.y = fmaf(ONE_M_A, xv.y + acc.y, ALPHA * hv.y);
    xo.z = fmaf(ONE_M_A, xv.z + acc.z, ALPHA * hv.z);
    xo.w = fmaf(ONE_M_A, xv.w + acc.w, ALPHA * hv.w);
    out_x[xr] = xo;
}

extern "C" void kernel_launch(void* const* d_in, const int* in_sizes, int n_in,
                              void* d_out, int out_size)
{
    const float4* x    = (const float4*)d_in[0];   // [N, D]
    const float4* nagg = (const float4*)d_in[1];   // [N, K, D]
    const float4* h    = (const float4*)d_in[2];   // [N, D]
    const float4* nbr  = (const float4*)d_in[3];   // [N, K, D]

    int n_nodes = in_sizes[0] / DDIM;              // N = |x| / D

    float4* out_x   = (float4*)d_out;                              // [N, D]
    float4* out_nbr = (float4*)d_out + (size_t)n_nodes * D4;       // [N, K, D]

    int total_threads = n_nodes * THREADS_PER_NODE;
    int block = 256;
    int grid  = (total_threads + block - 1) / block;

    appnp_fused_kernel<<<grid, block>>>(x, nagg, h, nbr, out_x, out_nbr, n_nodes);
}

// round 2
// speedup vs baseline: 1.0305x; 1.0305x over previous
#include <cuda_runtime.h>

// GraphAppnp: fused sum-aggregation + APPNP alpha blend. HBM-bound streaming.
// Inputs: x[N,D], neighbor_agg[N,K,D], h[N,D], neighbor[N,K,D]
// Outputs (concat): x_out[N,D] then nbr_out[N,K,D]
// N=50000, K=32, D=64, ALPHA=0.1

#define ALPHA     0.1f
#define ONE_M_A   0.9f
#define KNBR      32
#define DDIM      64
#define D4        16          // D/4 float4 per row
#define KBATCH    4           // k-slices batched per load/store group

__global__ __launch_bounds__(256, 3)
void appnp_fused_kernel(const float4* __restrict__ x,
                        const float4* __restrict__ nagg,
                        const float4* __restrict__ h,
                        const float4* __restrict__ nbr,
                        float4* __restrict__ out_x,
                        float4* __restrict__ out_nbr,
                        int n_nodes)
{
    int gtid = blockIdx.x * blockDim.x + threadIdx.x;
    int node = gtid >> 4;
    int d4   = gtid & 15;
    if (node >= n_nodes) return;

    size_t row_base = (size_t)node * (KNBR * D4) + d4;
    const float4* na_p  = nagg    + row_base;
    const float4* nb_p  = nbr     + row_base;
    float4*       out_p = out_nbr + row_base;

    size_t xr = (size_t)node * D4 + d4;
    float4 xv = x[xr];

    float4 acc = make_float4(0.f, 0.f, 0.f, 0.f);

    #pragma unroll
    for (int kb = 0; kb < KNBR / KBATCH; ++kb) {
        float4 a[KBATCH], b[KBATCH];

        // batched streaming loads (evict-first): long same-direction read burst
        #pragma unroll
        for (int j = 0; j < KBATCH; ++j) {
            size_t off = (size_t)(kb * KBATCH + j) * D4;
            a[j] = __ldcs(na_p + off);
            b[j] = __ldcs(nb_p + off);
        }

        float4 o[KBATCH];
        #pragma unroll
        for (int j = 0; j < KBATCH; ++j) {
            acc.x += a[j].x; acc.y += a[j].y; acc.z += a[j].z; acc.w += a[j].w;
            o[j].x = fmaf(ONE_M_A, a[j].x + xv.x, ALPHA * b[j].x);
            o[j].y = fmaf(ONE_M_A, a[j].y + xv.y, ALPHA * b[j].y);
            o[j].z = fmaf(ONE_M_A, a[j].z + xv.z, ALPHA * b[j].z);
            o[j].w = fmaf(ONE_M_A, a[j].w + xv.w, ALPHA * b[j].w);
        }

        // batched streaming stores: long write burst
        #pragma unroll
        for (int j = 0; j < KBATCH; ++j) {
            size_t off = (size_t)(kb * KBATCH + j) * D4;
            __stcs(out_p + off, o[j]);
        }
    }

    float4 hv = h[xr];
    float4 xo;
    xo.x = fmaf(ONE_M_A, xv.x + acc.x, ALPHA * hv.x);
    xo.y = fmaf(ONE_M_A, xv.y + acc.y, ALPHA * hv.y);
    xo.z = fmaf(ONE_M_A, xv.z + acc.z, ALPHA * hv.z);
    xo.w = fmaf(ONE_M_A, xv.w + acc.w, ALPHA * hv.w);
    out_x[xr] = xo;
}

extern "C" void kernel_launch(void* const* d_in, const int* in_sizes, int n_in,
                              void* d_out, int out_size)
{
    const float4* x    = (const float4*)d_in[0];
    const float4* nagg = (const float4*)d_in[1];
    const float4* h    = (const float4*)d_in[2];
    const float4* nbr  = (const float4*)d_in[3];

    int n_nodes = in_sizes[0] / DDIM;

    float4* out_x   = (float4*)d_out;
    float4* out_nbr = (float4*)d_out + (size_t)n_nodes * D4;

    int total_threads = n_nodes * 16;
    int block = 256;
    int grid  = (total_threads + block - 1) / block;

    appnp_fused_kernel<<<grid, block>>>(x, nagg, h, nbr, out_x, out_nbr, n_nodes);
}